// round 16
// baseline (speedup 1.0000x reference)
#include <cuda_runtime.h>
#include <cuda_fp16.h>
#include <cstdint>

// ---------------------------------------------------------------------------
// CrossAttentionDecoder, fp16 mma.sync GEMMs + fp16 scratch (q/k/v halved):
//   q = x@Wq^T (fp16 out) ; k,v = l@W^T on DENSELY PACKED live rows (fp16 out)
//   attn per (b,h): fp16 smem, full-K tile, fp32 softmax/accum ; out fp32.
// ---------------------------------------------------------------------------

#define NHEADS 8
#define DH 64
#define DIM 512
#define NLAT 128
#define NTOK 16
#define NB 1024
#define QROWS (NB * NTOK)      // 16384
#define KVROWS (NB * NLAT)     // 131072
#define LIVE_PER_PERIOD 8256
#define PACKED_TILES 516

__device__ __half g_qh[QROWS  * DIM];   //  17 MB
__device__ __half g_kh[KVROWS * DIM];   // 134 MB
__device__ __half g_vh[KVROWS * DIM];   // 134 MB
__device__ float  g_ao[QROWS  * DIM];   //  34 MB

__device__ __forceinline__ uint32_t packh2(float lo, float hi) {
    __half2 h = __floats2half2_rn(lo, hi);
    return *reinterpret_cast<uint32_t*>(&h);
}
__device__ __forceinline__ float2 h2f(uint32_t u) {
    return __half22float2(*reinterpret_cast<__half2*>(&u));
}
__device__ __forceinline__ void mma_f16(float* d, const uint32_t* a, const uint32_t* b) {
    asm volatile(
        "mma.sync.aligned.m16n8k16.row.col.f32.f16.f16.f32 "
        "{%0,%1,%2,%3}, {%4,%5,%6,%7}, {%8,%9}, {%0,%1,%2,%3};"
        : "+f"(d[0]), "+f"(d[1]), "+f"(d[2]), "+f"(d[3])
        : "r"(a[0]), "r"(a[1]), "r"(a[2]), "r"(a[3]), "r"(b[0]), "r"(b[1]));
}

// live-row index t -> global latent row (b*128 + j)
__device__ __forceinline__ int map_row(int t) {
    const int P  = t / LIVE_PER_PERIOD;
    const int tp = t - P * LIVE_PER_PERIOD;
    int m = (int)((sqrtf((float)(8 * tp + 1)) - 1.0f) * 0.5f);
    while ((m + 1) * (m + 2) / 2 <= tp) m++;
    while (m * (m + 1) / 2 > tp) m--;
    const int j = tp - m * (m + 1) / 2;
    return ((P << 7) + m) * 128 + j;
}

// Packed fp16x2 smem tile (proven): word(x,kp) @ (kp&3)*264 + x*2 + (kp>>2)
#define TILE16 1056
#define STAGE_W (2 * TILE16)

__device__ __forceinline__ void stage_ld_row(const float* __restrict__ rowp, int kh,
                                             float4* pv) {
    #pragma unroll
    for (int t = 0; t < 2; t++) {
        const float* p = rowp + t * 16 + kh * 8;
        pv[t * 2 + 0] = *reinterpret_cast<const float4*>(p);
        pv[t * 2 + 1] = *reinterpret_cast<const float4*>(p + 4);
    }
}
__device__ __forceinline__ void stage_st(uint32_t* __restrict__ dst, int x, int kh,
                                         const float4* pv) {
    #pragma unroll
    for (int t = 0; t < 2; t++) {
        const float4 lo = pv[t * 2 + 0], hi = pv[t * 2 + 1];
        uint32_t* base = dst + t * TILE16 + x * 2 + kh;
        base[0]   = packh2(lo.x, lo.y);
        base[264] = packh2(lo.z, lo.w);
        base[528] = packh2(hi.x, hi.y);
        base[792] = packh2(hi.z, hi.w);
    }
}

// ---------------------------------------------------------------------------
// Core mainloop (R10 skeleton). HOUT: fp16 epilogue. crow in elements.
// ---------------------------------------------------------------------------
template<bool BIAS, bool HOUT>
__device__ __forceinline__ void gemm_body(
    const float* __restrict__ Arow, const float* __restrict__ Bg,
    const float* __restrict__ bias, void* __restrict__ Cv,
    const size_t* __restrict__ crow, int n0)
{
    __shared__ __align__(16) uint32_t Abuf[2][STAGE_W];
    __shared__ __align__(16) uint32_t Bbuf[2][STAGE_W];

    const int tid  = threadIdx.x;
    const int lane = tid & 31;
    const int warp = tid >> 5;
    const int wm   = warp >> 1;
    const int wn   = warp & 1;
    const int x    = tid >> 1;
    const int kh   = tid & 1;
    const int r    = lane >> 2;
    const int c    = lane & 3;

    const float* Brow = Bg + (size_t)x * DIM;

    float acc[2][8][4];
    #pragma unroll
    for (int ma = 0; ma < 2; ma++)
        #pragma unroll
        for (int na = 0; na < 8; na++)
            #pragma unroll
            for (int q = 0; q < 4; q++) acc[ma][na][q] = 0.f;

    float4 pa[4], pb[4];
    stage_ld_row(Arow, kh, pa);
    stage_ld_row(Brow, kh, pb);
    stage_st(Abuf[0], x, kh, pa);
    stage_st(Bbuf[0], x, kh, pb);
    __syncthreads();

    #pragma unroll 1
    for (int it = 0; it < 16; it++) {
        const int buf = it & 1;
        if (it + 1 < 16) {
            stage_ld_row(Arow + (it + 1) * 32, kh, pa);
            stage_ld_row(Brow + (it + 1) * 32, kh, pb);
        }
        #pragma unroll
        for (int t = 0; t < 2; t++) {
            const uint32_t* Ab = &Abuf[buf][t * TILE16 + c * 264];
            const uint32_t* Bb = &Bbuf[buf][t * TILE16 + c * 264];
            uint32_t af[2][4];
            #pragma unroll
            for (int ma = 0; ma < 2; ma++) {
                const int mb = wm * 32 + ma * 16;
                const uint2 u0 = *reinterpret_cast<const uint2*>(Ab + (mb + r) * 2);
                const uint2 u1 = *reinterpret_cast<const uint2*>(Ab + (mb + r + 8) * 2);
                af[ma][0] = u0.x; af[ma][1] = u1.x; af[ma][2] = u0.y; af[ma][3] = u1.y;
            }
            #pragma unroll
            for (int na = 0; na < 8; na++) {
                const int nb = wn * 64 + na * 8;
                const uint2 bv = *reinterpret_cast<const uint2*>(Bb + (nb + r) * 2);
                uint32_t bf[2] = { bv.x, bv.y };
                mma_f16(acc[0][na], af[0], bf);
                mma_f16(acc[1][na], af[1], bf);
            }
        }
        if (it + 1 < 16) {
            stage_st(Abuf[buf ^ 1], x, kh, pa);
            stage_st(Bbuf[buf ^ 1], x, kh, pb);
            __syncthreads();
        }
    }

    const int cq = c * 2;
    #pragma unroll
    for (int ma = 0; ma < 2; ma++) {
        #pragma unroll
        for (int half = 0; half < 2; half++) {
            const int a0 = half * 2;
            #pragma unroll
            for (int na = 0; na < 8; na++) {
                const int col = n0 + wn * 64 + na * 8 + cq;
                if (HOUT) {
                    __half* C = (__half*)Cv;
                    *reinterpret_cast<__half2*>(C + crow[ma * 2 + half] + col) =
                        __floats2half2_rn(acc[ma][na][a0], acc[ma][na][a0 + 1]);
                } else {
                    float* C = (float*)Cv;
                    float b0 = 0.f, b1 = 0.f;
                    if (BIAS) { b0 = bias[col]; b1 = bias[col + 1]; }
                    *reinterpret_cast<float2*>(C + crow[ma * 2 + half] + col) =
                        make_float2(acc[ma][na][a0] + b0, acc[ma][na][a0 + 1] + b1);
                }
            }
        }
    }
}

template<bool BIAS, bool HOUT>
__global__ __launch_bounds__(256, 2)
void gemm_f16(const float* __restrict__ A, const float* __restrict__ B,
              const float* __restrict__ bias, void* __restrict__ C)
{
    const size_t m0 = (size_t)blockIdx.y * 128;
    const int    n0 = blockIdx.x * 128;
    const int tid = threadIdx.x, lane = tid & 31, warp = tid >> 5;
    const int wm = warp >> 1, r = lane >> 2;

    const float* Arow = A + (m0 + (tid >> 1)) * DIM;
    size_t crow[4];
    #pragma unroll
    for (int ma = 0; ma < 2; ma++) {
        crow[ma * 2 + 0] = (m0 + wm * 32 + ma * 16 + r) * DIM;
        crow[ma * 2 + 1] = (m0 + wm * 32 + ma * 16 + r + 8) * DIM;
    }
    gemm_body<BIAS, HOUT>(Arow, B + (size_t)n0 * DIM, bias, C, crow, n0);
}

__global__ __launch_bounds__(256, 2)
void gemm_f16_packed(const float* __restrict__ A, const float* __restrict__ B,
                     __half* __restrict__ C)
{
    const int t0 = blockIdx.y * 128;
    const int n0 = blockIdx.x * 128;
    const int tid = threadIdx.x, lane = tid & 31, warp = tid >> 5;
    const int wm = warp >> 1, r = lane >> 2;

    const float* Arow = A + (size_t)map_row(t0 + (tid >> 1)) * DIM;
    size_t crow[4];
    #pragma unroll
    for (int ma = 0; ma < 2; ma++) {
        crow[ma * 2 + 0] = (size_t)map_row(t0 + wm * 32 + ma * 16 + r) * DIM;
        crow[ma * 2 + 1] = (size_t)map_row(t0 + wm * 32 + ma * 16 + r + 8) * DIM;
    }
    gemm_body<false, true>(Arow, B + (size_t)n0 * DIM, nullptr, C, crow, n0);
}

// ---------------------------------------------------------------------------
// Attention, fp16 inputs/smem, fp32 math. One block per (b,h), 128 threads.
// Full 128-latent K tile in smem (fp16), scores reg-tiled 2 q-rows x 8 j.
// ---------------------------------------------------------------------------
#define KSTR 36   // uint32 words per 64-half row (32 + 4 pad; 144B, 16B-aligned)
__global__ __launch_bounds__(128, 6)
void attn_kernel(const __half* __restrict__ qb, const __half* __restrict__ kb,
                 const __half* __restrict__ vb, float* __restrict__ ob)
{
    __shared__ __align__(16) uint32_t qs [16 * KSTR];
    __shared__ __align__(16) uint32_t kvs[128 * KSTR];
    __shared__ float ss[16 * 132];
    __shared__ float red[16][17];
    __shared__ float rowmax[16], rinv[16];

    const int tid = threadIdx.x;
    const int bh  = blockIdx.x;
    const int b   = bh >> 3;
    const int h   = bh & 7;
    const int L   = (b & 127) + 1;

    const __half* qsrc = qb + (size_t)(b * NTOK) * DIM + h * DH;
    const __half* ksrc = kb + (size_t)(b * NLAT) * DIM + h * DH;
    const __half* vsrc = vb + (size_t)(b * NLAT) * DIM + h * DH;

    // stage q: 16 rows x 8 uint4
    {
        const int rr = tid >> 3, w = tid & 7;
        *reinterpret_cast<uint4*>(qs + rr * KSTR + w * 4) =
            *reinterpret_cast<const uint4*>(qsrc + (size_t)rr * DIM + w * 8);
    }
    // stage K rows < L
    for (int idx = tid; idx < 128 * 8; idx += 128) {
        const int j = idx >> 3, w = idx & 7;
        if (j < L)
            *reinterpret_cast<uint4*>(kvs + j * KSTR + w * 4) =
                *reinterpret_cast<const uint4*>(ksrc + (size_t)j * DIM + w * 8);
    }
    __syncthreads();

    // ---- scores: thread (i2 = tid&7 -> rows {i2, i2+8}; g = tid>>3 -> j grp) ----
    const int i2 = tid & 7;
    const int g  = tid >> 3;           // 0..15, latents g*8..g*8+7
    float m0r = -1e30f, m1r = -1e30f;
    if (g * 8 < L) {
        float sc0[8], sc1[8];
        #pragma unroll
        for (int jj = 0; jj < 8; jj++) { sc0[jj] = 0.f; sc1[jj] = 0.f; }
        #pragma unroll 2
        for (int d = 0; d < 8; d++) {          // 8 halfs per step
            const uint4 qa = *reinterpret_cast<const uint4*>(qs + i2 * KSTR + d * 4);
            const uint4 qc = *reinterpret_cast<const uint4*>(qs + (i2 + 8) * KSTR + d * 4);
            const float2 qa0 = h2f(qa.x), qa1 = h2f(qa.y), qa2 = h2f(qa.z), qa3 = h2f(qa.w);
            const float2 qc0 = h2f(qc.x), qc1 = h2f(qc.y), qc2 = h2f(qc.z), qc3 = h2f(qc.w);
            #pragma unroll
            for (int jj = 0; jj < 8; jj++) {
                const uint4 kv = *reinterpret_cast<const uint4*>(kvs + (g * 8 + jj) * KSTR + d * 4);
                const float2 k0 = h2f(kv.x), k1 = h2f(kv.y), k2 = h2f(kv.z), k3 = h2f(kv.w);
                sc0[jj] = fmaf(qa0.x, k0.x, fmaf(qa0.y, k0.y, fmaf(qa1.x, k1.x, fmaf(qa1.y, k1.y,
                          fmaf(qa2.x, k2.x, fmaf(qa2.y, k2.y, fmaf(qa3.x, k3.x, fmaf(qa3.y, k3.y, sc0[jj]))))))));
                sc1[jj] = fmaf(qc0.x, k0.x, fmaf(qc0.y, k0.y, fmaf(qc1.x, k1.x, fmaf(qc1.y, k1.y,
                          fmaf(qc2.x, k2.x, fmaf(qc2.y, k2.y, fmaf(qc3.x, k3.x, fmaf(qc3.y, k3.y, sc1[jj]))))))));
            }
        }
        #pragma unroll
        for (int jj = 0; jj < 8; jj++) {
            const int j = g * 8 + jj;
            if (j < L) {
                const float s0 = sc0[jj] * 0.125f, s1 = sc1[jj] * 0.125f;
                ss[i2 * 132 + j] = s0;        m0r = fmaxf(m0r, s0);
                ss[(i2 + 8) * 132 + j] = s1;  m1r = fmaxf(m1r, s1);
            }
        }
    }
    red[i2][g] = m0r;
    red[i2 + 8][g] = m1r;
    __syncthreads();

    if (tid < 16) {
        float m = red[tid][0];
        #pragma unroll
        for (int t = 1; t < 16; t++) m = fmaxf(m, red[tid][t]);
        rowmax[tid] = m;
    }
    // stage V (kvs free after scores)
    for (int idx = tid; idx < 128 * 8; idx += 128) {
        const int j = idx >> 3, w = idx & 7;
        if (j < L)
            *reinterpret_cast<uint4*>(kvs + j * KSTR + w * 4) =
                *reinterpret_cast<const uint4*>(vsrc + (size_t)j * DIM + w * 8);
    }
    __syncthreads();

    // ---- exp + sum: thread (i = tid&15, g2 = tid>>4 -> 16 j) ----
    const int i  = tid & 15;
    const int g2 = tid >> 4;
    {
        const float m = rowmax[i];
        float s = 0.f;
        #pragma unroll
        for (int jj = 0; jj < 16; jj++) {
            const int j = g2 * 16 + jj;
            if (j < L) {
                const float e = __expf(ss[i * 132 + j] - m);
                ss[i * 132 + j] = e;
                s += e;
            }
        }
        red[i][g2] = s;
    }
    __syncthreads();
    if (tid < 16) {
        float s = red[tid][0];
        #pragma unroll
        for (int t = 1; t < 8; t++) s += red[tid][t];
        rinv[tid] = 1.f / s;
    }
    __syncthreads();

    // ---- PV: thread (i, g2) -> out dims g2*8..g2*8+7 ----
    float acc[8];
    #pragma unroll
    for (int rr = 0; rr < 8; rr++) acc[rr] = 0.f;
    for (int j = 0; j < L; j++) {
        const float p = ss[i * 132 + j];
        const uint4 vv = *reinterpret_cast<const uint4*>(kvs + j * KSTR + g2 * 4);
        const float2 v0 = h2f(vv.x), v1 = h2f(vv.y), v2 = h2f(vv.z), v3 = h2f(vv.w);
        acc[0] = fmaf(p, v0.x, acc[0]); acc[1] = fmaf(p, v0.y, acc[1]);
        acc[2] = fmaf(p, v1.x, acc[2]); acc[3] = fmaf(p, v1.y, acc[3]);
        acc[4] = fmaf(p, v2.x, acc[4]); acc[5] = fmaf(p, v2.y, acc[5]);
        acc[6] = fmaf(p, v3.x, acc[6]); acc[7] = fmaf(p, v3.y, acc[7]);
    }
    const float inv = rinv[i];
    float* dst = ob + (size_t)(b * NTOK + i) * DIM + h * DH + g2 * 8;
    *reinterpret_cast<float4*>(dst) =
        make_float4(acc[0] * inv, acc[1] * inv, acc[2] * inv, acc[3] * inv);
    *reinterpret_cast<float4*>(dst + 4) =
        make_float4(acc[4] * inv, acc[5] * inv, acc[6] * inv, acc[7] * inv);
}

// ---------------------------------------------------------------------------
extern "C" void kernel_launch(void* const* d_in, const int* in_sizes, int n_in,
                              void* d_out, int out_size)
{
    const float* x  = (const float*)d_in[0];
    const float* l  = (const float*)d_in[1];
    const float* Wq = (const float*)d_in[2];
    const float* Wk = (const float*)d_in[3];
    const float* Wv = (const float*)d_in[4];
    const float* Wo = (const float*)d_in[5];
    const float* bo = (const float*)d_in[6];
    float* out = (float*)d_out;

    void *pq, *pk, *pv, *pa;
    cudaGetSymbolAddress(&pq, g_qh);
    cudaGetSymbolAddress(&pk, g_kh);
    cudaGetSymbolAddress(&pv, g_vh);
    cudaGetSymbolAddress(&pa, g_ao);
    __half* qh = (__half*)pq;
    __half* kh = (__half*)pk;
    __half* vh = (__half*)pv;
    float*  ao = (float*)pa;

    dim3 blk(256);
    gemm_f16<false, true><<<dim3(4, QROWS / 128), blk>>>(x, Wq, nullptr, qh);
    gemm_f16_packed<<<dim3(4, PACKED_TILES), blk>>>(l, Wk, kh);
    gemm_f16_packed<<<dim3(4, PACKED_TILES), blk>>>(l, Wv, vh);
    attn_kernel<<<NB * NHEADS, 128>>>(qh, kh, vh, ao);
    gemm_f16<true, false><<<dim3(4, QROWS / 128), blk>>>(ao, Wo, bo, out);
}